// round 2
// baseline (speedup 1.0000x reference)
#include <cuda_runtime.h>

#define MAX_NODES 100000
#define D 128

// Scratch: combined = (1+eps)*features + neighbor_sum, eps = 0.
__device__ float g_comb[(size_t)MAX_NODES * D];

// ---------------------------------------------------------------------------
// Kernel 1: init combined = features (vectorized copy, float4 grid-stride)
// ---------------------------------------------------------------------------
__global__ void init_combined(const float* __restrict__ feat, int n_vec4) {
    int i = blockIdx.x * blockDim.x + threadIdx.x;
    if (i < n_vec4) {
        reinterpret_cast<float4*>(g_comb)[i] =
            reinterpret_cast<const float4*>(feat)[i];
    }
}

// ---------------------------------------------------------------------------
// Kernel 2: edge scatter. One warp per edge: 32 lanes x float4 = 128 floats.
// combined[row[e]] += values[e] * features[col[e]] via red.global.add.v4.f32
// ---------------------------------------------------------------------------
__global__ void __launch_bounds__(256) edge_scatter(
    const int* __restrict__ row_idx, const int* __restrict__ col_idx,
    const float* __restrict__ val, const float* __restrict__ feat, int n_edges)
{
    int e = blockIdx.x * 8 + (threadIdx.x >> 5);
    int lane = threadIdx.x & 31;
    if (e >= n_edges) return;

    int r = __ldg(row_idx + e);
    int c = __ldg(col_idx + e);
    float v = __ldg(val + e);

    const float4 f = *reinterpret_cast<const float4*>(
        feat + (size_t)c * D + lane * 4);
    float mx = f.x * v, my = f.y * v, mz = f.z * v, mw = f.w * v;

    float* dst = g_comb + (size_t)r * D + lane * 4;
    asm volatile("red.global.add.v4.f32 [%0], {%1, %2, %3, %4};"
                 :: "l"(dst), "f"(mx), "f"(my), "f"(mz), "f"(mw)
                 : "memory");
}

// ---------------------------------------------------------------------------
// Kernel 3: fused MLP: out = relu(X @ W1 + b1) @ W2 + b2
// Block tile: 64 nodes x 128 cols. 256 threads; thread = 8 nodes x 4 cols.
// X tile (and then H tile) in 32KB smem. W rows streamed via LDG.128
// (W1+W2 = 128KB, L1-resident per SM after warmup).
// ---------------------------------------------------------------------------
__global__ void __launch_bounds__(256) fused_mlp(
    const float* __restrict__ W1, const float* __restrict__ b1,
    const float* __restrict__ W2, const float* __restrict__ b2,
    float* __restrict__ out, int n_nodes)
{
    __shared__ float xs[64][D];   // 32 KB, reused for X then H

    const int tid  = threadIdx.x;
    const int cg   = tid & 31;    // col group: cols cg*4 .. cg*4+3
    const int ng   = tid >> 5;    // node group: nodes ng*8 .. ng*8+7
    const int node0 = blockIdx.x * 64;

    // --- load X tile (64 rows x 32 float4 = 2048 vec4; 8 per thread) ---
    #pragma unroll
    for (int i = 0; i < 8; i++) {
        int idx  = tid + i * 256;
        int nrow = idx >> 5;
        int c4   = idx & 31;
        int gn   = node0 + nrow;
        float4 vv = (gn < n_nodes)
            ? reinterpret_cast<const float4*>(g_comb + (size_t)gn * D)[c4]
            : make_float4(0.f, 0.f, 0.f, 0.f);
        reinterpret_cast<float4*>(&xs[nrow][0])[c4] = vv;
    }
    __syncthreads();

    float acc[8][4];

    // --- GEMM1: H = relu(X @ W1 + b1) ---
    {
        float4 bb = __ldg(reinterpret_cast<const float4*>(b1) + cg);
        #pragma unroll
        for (int i = 0; i < 8; i++) {
            acc[i][0] = bb.x; acc[i][1] = bb.y;
            acc[i][2] = bb.z; acc[i][3] = bb.w;
        }
    }
    #pragma unroll 4
    for (int k = 0; k < D; k++) {
        float4 w = __ldg(reinterpret_cast<const float4*>(W1 + k * D) + cg);
        #pragma unroll
        for (int i = 0; i < 8; i++) {
            float x = xs[ng * 8 + i][k];
            acc[i][0] = fmaf(x, w.x, acc[i][0]);
            acc[i][1] = fmaf(x, w.y, acc[i][1]);
            acc[i][2] = fmaf(x, w.z, acc[i][2]);
            acc[i][3] = fmaf(x, w.w, acc[i][3]);
        }
    }
    __syncthreads();   // all reads of xs (X) complete before overwrite

    // --- write H (relu) into xs ---
    #pragma unroll
    for (int i = 0; i < 8; i++) {
        float4 h4 = make_float4(fmaxf(acc[i][0], 0.f), fmaxf(acc[i][1], 0.f),
                                fmaxf(acc[i][2], 0.f), fmaxf(acc[i][3], 0.f));
        reinterpret_cast<float4*>(&xs[ng * 8 + i][0])[cg] = h4;
    }
    __syncthreads();

    // --- GEMM2: OUT = H @ W2 + b2 ---
    {
        float4 bb = __ldg(reinterpret_cast<const float4*>(b2) + cg);
        #pragma unroll
        for (int i = 0; i < 8; i++) {
            acc[i][0] = bb.x; acc[i][1] = bb.y;
            acc[i][2] = bb.z; acc[i][3] = bb.w;
        }
    }
    #pragma unroll 4
    for (int k = 0; k < D; k++) {
        float4 w = __ldg(reinterpret_cast<const float4*>(W2 + k * D) + cg);
        #pragma unroll
        for (int i = 0; i < 8; i++) {
            float x = xs[ng * 8 + i][k];
            acc[i][0] = fmaf(x, w.x, acc[i][0]);
            acc[i][1] = fmaf(x, w.y, acc[i][1]);
            acc[i][2] = fmaf(x, w.z, acc[i][2]);
            acc[i][3] = fmaf(x, w.w, acc[i][3]);
        }
    }

    // --- store ---
    #pragma unroll
    for (int i = 0; i < 8; i++) {
        int gn = node0 + ng * 8 + i;
        if (gn < n_nodes) {
            reinterpret_cast<float4*>(out + (size_t)gn * D)[cg] =
                make_float4(acc[i][0], acc[i][1], acc[i][2], acc[i][3]);
        }
    }
}

// ---------------------------------------------------------------------------
// Launch. Input order (metadata): indices(2,E) i32, values(E) f32,
// features(N,128) f32, W1(128,128), b1(128), W2(128,128), b2(128).
// ---------------------------------------------------------------------------
extern "C" void kernel_launch(void* const* d_in, const int* in_sizes, int n_in,
                              void* d_out, int out_size)
{
    const int*   indices  = (const int*)d_in[0];
    const float* values   = (const float*)d_in[1];
    const float* features = (const float*)d_in[2];
    const float* W1       = (const float*)d_in[3];
    const float* b1       = (const float*)d_in[4];
    const float* W2       = (const float*)d_in[5];
    const float* b2       = (const float*)d_in[6];
    float*       out      = (float*)d_out;

    const int n_edges = in_sizes[1];
    const int n_nodes = in_sizes[2] / D;

    const int* row_idx = indices;
    const int* col_idx = indices + n_edges;

    // 1) combined = features
    {
        int n_vec4 = n_nodes * (D / 4);
        int blocks = (n_vec4 + 255) / 256;
        init_combined<<<blocks, 256>>>(features, n_vec4);
    }

    // 2) combined[row] += v * features[col]  (warp per edge, v4 reductions)
    {
        int blocks = (n_edges + 7) / 8;
        edge_scatter<<<blocks, 256>>>(row_idx, col_idx, values, features,
                                      n_edges);
    }

    // 3) out = relu(combined @ W1 + b1) @ W2 + b2
    {
        int blocks = (n_nodes + 63) / 64;
        fused_mlp<<<blocks, 256>>>(W1, b1, W2, b2, out, n_nodes);
    }
}